// round 1
// baseline (speedup 1.0000x reference)
#include <cuda_runtime.h>
#include <cuda_bf16.h>
#include <math.h>
#include <stdint.h>

// ---------------- problem constants (fixed by setup_inputs) ----------------
#define BSZ   2
#define LSEQ  2048
#define DM    1024
#define DIN   2048          // 2*DM
#define NST   16
#define KCONV 4
#define DTR   64            // dt_rank = DM/16
#define MROWS (BSZ*LSEQ)    // 4096
#define XZC   (2*DIN)       // 4096
#define DBCC  (DTR + 2*NST) // 96

// ---------------- scratch (static device allocations; no cudaMalloc) -------
__device__ float g_xn[MROWS * DM];       // 16 MB  layernorm output
__device__ float g_xz[MROWS * XZC];      // 64 MB  [u | z]
__device__ float g_uc[MROWS * DIN];      // 32 MB  silu(conv(u))
__device__ float g_dbc[MROWS * DBCC];    // 1.5 MB [dt | B | C]
__device__ float g_delta[MROWS * DIN];   // 32 MB
__device__ float g_gt[MROWS * DIN];      // 32 MB  gated scan output

// ---------------- layernorm ----------------
__global__ void ln_kernel(const float* __restrict__ x,
                          const float* __restrict__ lng,
                          const float* __restrict__ lnb)
{
    int row = blockIdx.x;
    const float* xr = x + (size_t)row * DM;
    float s = 0.f, s2 = 0.f;
    for (int i = threadIdx.x; i < DM; i += 256) {
        float v = xr[i];
        s += v; s2 += v * v;
    }
    #pragma unroll
    for (int o = 16; o; o >>= 1) {
        s  += __shfl_xor_sync(0xffffffffu, s,  o);
        s2 += __shfl_xor_sync(0xffffffffu, s2, o);
    }
    __shared__ float red[2][8];
    int w = threadIdx.x >> 5;
    if ((threadIdx.x & 31) == 0) { red[0][w] = s; red[1][w] = s2; }
    __syncthreads();
    __shared__ float stats[2];
    if (threadIdx.x == 0) {
        float a = 0.f, b2 = 0.f;
        #pragma unroll
        for (int i = 0; i < 8; i++) { a += red[0][i]; b2 += red[1][i]; }
        float mean = a / (float)DM;
        float var  = b2 / (float)DM - mean * mean;
        stats[0] = mean;
        stats[1] = rsqrtf(var + 1e-5f);
    }
    __syncthreads();
    float mean = stats[0], rstd = stats[1];
    float* out = g_xn + (size_t)row * DM;
    for (int i = threadIdx.x; i < DM; i += 256)
        out[i] = (xr[i] - mean) * rstd * lng[i] + lnb[i];
}

// ---------------- generic SGEMM: C = A(MxK) * B(KxN), row-major ------------
// EPI: 0 = plain, 1 = softplus(acc + bias[col]), 2 = acc + res[row*N+col]
__device__ __forceinline__ float softplusf(float x) {
    if (x > 20.f) return x;
    return log1pf(expf(x));
}

template <int EPI>
__global__ void __launch_bounds__(256, 2)
sgemm_k(const float* __restrict__ A, int lda,
        const float* __restrict__ Bm, int ldb,
        float* __restrict__ C, int ldc,
        int M, int Nn, int Kk,
        const float* __restrict__ bias,
        const float* __restrict__ res)
{
    __shared__ float As[16][132];
    __shared__ float Bs[16][128];

    int tid = threadIdx.x;
    int tx = tid & 15, ty = tid >> 4;
    int bm0 = blockIdx.y * 128, bn0 = blockIdx.x * 128;

    float acc[8][8];
    #pragma unroll
    for (int i = 0; i < 8; i++)
        #pragma unroll
        for (int j = 0; j < 8; j++) acc[i][j] = 0.f;

    for (int k0 = 0; k0 < Kk; k0 += 16) {
        // A tile: 128x16, float4 along K (K is always a multiple of 16 here)
        #pragma unroll
        for (int it = 0; it < 2; it++) {
            int id  = tid + it * 256;
            int ar  = id >> 2;
            int ac4 = (id & 3) * 4;
            const float* Ap = A + (size_t)(bm0 + ar) * lda + k0 + ac4;
            float4 v = *(const float4*)Ap;
            As[ac4 + 0][ar] = v.x;
            As[ac4 + 1][ar] = v.y;
            As[ac4 + 2][ar] = v.z;
            As[ac4 + 3][ar] = v.w;
        }
        // B tile: 16x128, float4 along N, guarded for N not multiple of 128
        #pragma unroll
        for (int it = 0; it < 2; it++) {
            int id  = tid + it * 256;
            int br  = id >> 5;
            int bc4 = (id & 31) * 4;
            const float* Bp = Bm + (size_t)(k0 + br) * ldb + bn0 + bc4;
            float4 v;
            if (bn0 + bc4 + 3 < Nn) {
                v = *(const float4*)Bp;
            } else {
                v.x = (bn0 + bc4 + 0 < Nn) ? Bp[0] : 0.f;
                v.y = (bn0 + bc4 + 1 < Nn) ? Bp[1] : 0.f;
                v.z = (bn0 + bc4 + 2 < Nn) ? Bp[2] : 0.f;
                v.w = (bn0 + bc4 + 3 < Nn) ? Bp[3] : 0.f;
            }
            *(float4*)&Bs[br][bc4] = v;
        }
        __syncthreads();

        #pragma unroll
        for (int kk = 0; kk < 16; kk++) {
            float a[8], b[8];
            *(float4*)(a)     = *(const float4*)&As[kk][ty * 8];
            *(float4*)(a + 4) = *(const float4*)&As[kk][ty * 8 + 4];
            *(float4*)(b)     = *(const float4*)&Bs[kk][tx * 8];
            *(float4*)(b + 4) = *(const float4*)&Bs[kk][tx * 8 + 4];
            #pragma unroll
            for (int i = 0; i < 8; i++)
                #pragma unroll
                for (int j = 0; j < 8; j++)
                    acc[i][j] = fmaf(a[i], b[j], acc[i][j]);
        }
        __syncthreads();
    }

    #pragma unroll
    for (int i = 0; i < 8; i++) {
        int row = bm0 + ty * 8 + i;
        #pragma unroll
        for (int j = 0; j < 8; j++) {
            int col = bn0 + tx * 8 + j;
            if (col < Nn) {
                float v = acc[i][j];
                if (EPI == 1)      v = softplusf(v + bias[col]);
                else if (EPI == 2) v = v + res[(size_t)row * Nn + col];
                C[(size_t)row * ldc + col] = v;
            }
        }
    }
}

// ---------------- causal depthwise conv (k=4) + SiLU ----------------
__global__ void conv_silu_kernel(const float* __restrict__ cw,
                                 const float* __restrict__ cb)
{
    int idx = blockIdx.x * 256 + threadIdx.x;
    if (idx >= MROWS * DIN) return;
    int d = idx % DIN;
    int m = idx / DIN;
    int t = m % LSEQ;
    int base = m - t;   // b*L
    float acc = cb[d];
    #pragma unroll
    for (int j = 0; j < KCONV; j++) {
        int tt = t - (KCONV - 1) + j;
        if (tt >= 0)
            acc = fmaf(cw[d * KCONV + j], g_xz[(size_t)(base + tt) * XZC + d], acc);
    }
    float s = acc / (1.f + __expf(-acc));   // silu
    g_uc[idx] = s;
}

// ---------------- selective scan (+ u*D, + z gating) ----------------
// 16 lanes per (b,d) channel, one lane per state n; h kept in a register.
__global__ void scan_kernel(const float* __restrict__ A_log,
                            const float* __restrict__ Dp)
{
    int tid = blockIdx.x * blockDim.x + threadIdx.x;
    int grp = tid >> 4;          // channel index 0..B*DIN-1
    int n   = tid & 15;
    if (grp >= BSZ * DIN) return;
    int b = grp / DIN;
    int d = grp % DIN;

    float An = -expf(A_log[d * NST + n]);
    float Dd = Dp[d];

    const float* dbc_b = g_dbc   + (size_t)b * LSEQ * DBCC;
    const float* del_b = g_delta + (size_t)b * LSEQ * DIN + d;
    const float* u_b   = g_uc    + (size_t)b * LSEQ * DIN + d;
    const float* z_b   = g_xz    + (size_t)b * LSEQ * XZC + DIN + d;
    float*       o_b   = g_gt    + (size_t)b * LSEQ * DIN + d;

    float h = 0.f;
    for (int t = 0; t < LSEQ; t++) {
        float delta = del_b[(size_t)t * DIN];
        float u     = u_b[(size_t)t * DIN];
        float Bv    = dbc_b[(size_t)t * DBCC + DTR + n];
        float Cv    = dbc_b[(size_t)t * DBCC + DTR + NST + n];
        float da = __expf(delta * An);
        h = fmaf(da, h, delta * Bv * u);
        float p = h * Cv;
        p += __shfl_xor_sync(0xffffffffu, p, 8, 16);
        p += __shfl_xor_sync(0xffffffffu, p, 4, 16);
        p += __shfl_xor_sync(0xffffffffu, p, 2, 16);
        p += __shfl_xor_sync(0xffffffffu, p, 1, 16);
        if (n == 0) {
            float y = p + u * Dd;
            float z = z_b[(size_t)t * XZC];
            float g = y * (z / (1.f + __expf(-z)));
            o_b[(size_t)t * DIN] = g;
        }
    }
}

// ---------------- launcher ----------------
extern "C" void kernel_launch(void* const* d_in, const int* in_sizes, int n_in,
                              void* d_out, int out_size)
{
    const float* x         = (const float*)d_in[0];   // (B,L,Dm)
    const float* in_proj_w = (const float*)d_in[1];   // (Dm, 2*Din) = (1024,4096)
    const float* conv_w    = (const float*)d_in[2];   // (Din, 4)
    const float* conv_b    = (const float*)d_in[3];   // (Din,)
    const float* x_proj_w  = (const float*)d_in[4];   // (Din, 96)
    const float* dt_proj_w = (const float*)d_in[5];   // (64, Din)
    const float* dt_proj_b = (const float*)d_in[6];   // (Din,)
    const float* A_log     = (const float*)d_in[7];   // (Din, 16)
    const float* Dp        = (const float*)d_in[8];   // (Din,)
    const float* out_proj_w= (const float*)d_in[9];   // (Din, Dm)
    const float* ln_g      = (const float*)d_in[10];  // (Dm,)
    const float* ln_b      = (const float*)d_in[11];  // (Dm,)
    float* out = (float*)d_out;                       // (B,L,Dm)

    float* xn    = nullptr; cudaGetSymbolAddress((void**)&xn,    g_xn);
    float* xz    = nullptr; cudaGetSymbolAddress((void**)&xz,    g_xz);
    float* uc    = nullptr; cudaGetSymbolAddress((void**)&uc,    g_uc);
    float* dbc   = nullptr; cudaGetSymbolAddress((void**)&dbc,   g_dbc);
    float* delta = nullptr; cudaGetSymbolAddress((void**)&delta, g_delta);
    float* gt    = nullptr; cudaGetSymbolAddress((void**)&gt,    g_gt);

    // 1) layernorm
    ln_kernel<<<MROWS, 256>>>(x, ln_g, ln_b);

    // 2) xz = xn @ in_proj_w   (4096 x 4096, K=1024)
    {
        dim3 grid((XZC + 127) / 128, (MROWS + 127) / 128);
        sgemm_k<0><<<grid, 256>>>(xn, DM, in_proj_w, XZC, xz, XZC,
                                  MROWS, XZC, DM, nullptr, nullptr);
    }

    // 3) u = silu(causal_conv(xz[:, :Din]))
    conv_silu_kernel<<<(MROWS * DIN + 255) / 256, 256>>>(conv_w, conv_b);

    // 4) dbc = u @ x_proj_w    (4096 x 96, K=2048)
    {
        dim3 grid((DBCC + 127) / 128, (MROWS + 127) / 128);
        sgemm_k<0><<<grid, 256>>>(uc, DIN, x_proj_w, DBCC, dbc, DBCC,
                                  MROWS, DBCC, DIN, nullptr, nullptr);
    }

    // 5) delta = softplus(dbc[:, :64] @ dt_proj_w + dt_proj_b)  (4096 x 2048, K=64)
    {
        dim3 grid((DIN + 127) / 128, (MROWS + 127) / 128);
        sgemm_k<1><<<grid, 256>>>(dbc, DBCC, dt_proj_w, DIN, delta, DIN,
                                  MROWS, DIN, DTR, dt_proj_b, nullptr);
    }

    // 6) selective scan + D skip + z gating -> gt
    {
        int threads = BSZ * DIN * NST;  // 65536
        scan_kernel<<<(threads + 255) / 256, 256>>>(A_log, Dp);
    }

    // 7) out = x + gt @ out_proj_w  (4096 x 1024, K=2048)
    {
        dim3 grid((DM + 127) / 128, (MROWS + 127) / 128);
        sgemm_k<2><<<grid, 256>>>(gt, DIN, out_proj_w, DM, out, DM,
                                  MROWS, DM, DIN, nullptr, x);
    }
    (void)in_sizes; (void)n_in; (void)out_size;
}

// round 5
// speedup vs baseline: 1.4651x; 1.4651x over previous
#include <cuda_runtime.h>
#include <cuda_bf16.h>
#include <math.h>
#include <stdint.h>

// ---------------- problem constants (fixed by setup_inputs) ----------------
#define BSZ   2
#define LSEQ  2048
#define DM    1024
#define DIN   2048          // 2*DM
#define NST   16
#define KCONV 4
#define DTR   64            // dt_rank = DM/16
#define MROWS (BSZ*LSEQ)    // 4096
#define XZC   (2*DIN)       // 4096
#define DBCC  (DTR + 2*NST) // 96

// ---------------- scratch (static device arrays; no cudaMalloc) -------
__device__ float g_xn[MROWS * DM];       // layernorm output
__device__ float g_xz[MROWS * XZC];      // [u | z]
__device__ float g_uc[MROWS * DIN];      // silu(conv(u))
__device__ float g_dbc[MROWS * DBCC];    // [dt | B | C]
__device__ float g_delta[MROWS * DIN];
__device__ float g_gt[MROWS * DIN];      // gated scan output

// ---------------- layernorm ----------------
__global__ void ln_kernel(const float* __restrict__ x,
                          const float* __restrict__ lng,
                          const float* __restrict__ lnb)
{
    int row = blockIdx.x;
    const float* xr = x + (size_t)row * DM;
    float s = 0.f, s2 = 0.f;
    for (int i = threadIdx.x; i < DM; i += 256) {
        float v = xr[i];
        s += v; s2 += v * v;
    }
    #pragma unroll
    for (int o = 16; o; o >>= 1) {
        s  += __shfl_xor_sync(0xffffffffu, s,  o);
        s2 += __shfl_xor_sync(0xffffffffu, s2, o);
    }
    __shared__ float red[2][8];
    int w = threadIdx.x >> 5;
    if ((threadIdx.x & 31) == 0) { red[0][w] = s; red[1][w] = s2; }
    __syncthreads();
    __shared__ float stats[2];
    if (threadIdx.x == 0) {
        float a = 0.f, b2 = 0.f;
        #pragma unroll
        for (int i = 0; i < 8; i++) { a += red[0][i]; b2 += red[1][i]; }
        float mean = a / (float)DM;
        float var  = b2 / (float)DM - mean * mean;
        stats[0] = mean;
        stats[1] = rsqrtf(var + 1e-5f);
    }
    __syncthreads();
    float mean = stats[0], rstd = stats[1];
    float* out = g_xn + (size_t)row * DM;
    for (int i = threadIdx.x; i < DM; i += 256)
        out[i] = (xr[i] - mean) * rstd * lng[i] + lnb[i];
}

// ---------------- tf32 tensor-core GEMM -------------------------------
// C = A(MxK,row) * B(KxN,row).  BM=128 BN=128 BK=32, 8 warps.
// EPI: 0 plain, 1 softplus(acc+bias[col]), 2 acc+res[row*N+col]
__device__ __forceinline__ float softplusf(float x) {
    if (x > 20.f) return x;
    return log1pf(expf(x));
}
__device__ __forceinline__ uint32_t f2tf32(float f) {
    uint32_t r;
    asm("cvt.rna.tf32.f32 %0, %1;" : "=r"(r) : "f"(f));
    return r;
}
__device__ __forceinline__ void mma_tf32(float* c, const uint32_t* a, const uint32_t* b) {
    asm volatile(
        "mma.sync.aligned.m16n8k8.row.col.f32.tf32.tf32.f32 "
        "{%0,%1,%2,%3}, {%4,%5,%6,%7}, {%8,%9}, {%0,%1,%2,%3};"
        : "+f"(c[0]), "+f"(c[1]), "+f"(c[2]), "+f"(c[3])
        : "r"(a[0]), "r"(a[1]), "r"(a[2]), "r"(a[3]), "r"(b[0]), "r"(b[1]));
}

template <int EPI>
__global__ void __launch_bounds__(256)
mma_gemm(const float* __restrict__ A, int lda,
         const float* __restrict__ Bm, int ldb,
         float* __restrict__ C, int ldc,
         int M, int Nn, int Kk,
         const float* __restrict__ bias,
         const float* __restrict__ res)
{
    __shared__ uint32_t As[128][36];   // [m][k], pad 4
    __shared__ uint32_t Bs[32][132];   // [k][n], pad 4

    int tid  = threadIdx.x;
    int lane = tid & 31;
    int wid  = tid >> 5;
    int warp_m = wid >> 2;           // 0..1  (64 rows each)
    int warp_n = wid & 3;            // 0..3  (32 cols each)
    int bm0 = blockIdx.y * 128, bn0 = blockIdx.x * 128;

    float acc[16][4];                // [mi*4+ni][4]
    #pragma unroll
    for (int i = 0; i < 16; i++)
        #pragma unroll
        for (int j = 0; j < 4; j++) acc[i][j] = 0.f;

    int qrow = lane >> 2;            // 0..7
    int qcol = lane & 3;             // 0..3

    for (int k0 = 0; k0 < Kk; k0 += 32) {
        // A tile: 128 x 32, float4 along K
        #pragma unroll
        for (int it = 0; it < 4; it++) {
            int id  = tid + it * 256;
            int r   = id >> 3;
            int c4  = (id & 7) * 4;
            const float* Ap = A + (size_t)(bm0 + r) * lda + k0 + c4;
            float4 v = *(const float4*)Ap;
            As[r][c4 + 0] = f2tf32(v.x);
            As[r][c4 + 1] = f2tf32(v.y);
            As[r][c4 + 2] = f2tf32(v.z);
            As[r][c4 + 3] = f2tf32(v.w);
        }
        // B tile: 32 x 128, float4 along N (guarded for N<128 edge)
        #pragma unroll
        for (int it = 0; it < 4; it++) {
            int id  = tid + it * 256;
            int kr  = id >> 5;
            int nc4 = (id & 31) * 4;
            uint32_t w0 = 0, w1 = 0, w2 = 0, w3 = 0;
            if (bn0 + nc4 + 3 < Nn) {
                const float* Bp = Bm + (size_t)(k0 + kr) * ldb + bn0 + nc4;
                float4 v = *(const float4*)Bp;
                w0 = f2tf32(v.x); w1 = f2tf32(v.y);
                w2 = f2tf32(v.z); w3 = f2tf32(v.w);
            }
            Bs[kr][nc4 + 0] = w0;
            Bs[kr][nc4 + 1] = w1;
            Bs[kr][nc4 + 2] = w2;
            Bs[kr][nc4 + 3] = w3;
        }
        __syncthreads();

        #pragma unroll
        for (int kk = 0; kk < 4; kk++) {
            int kb = kk * 8;
            uint32_t af[4][4];
            #pragma unroll
            for (int mi = 0; mi < 4; mi++) {
                int m0 = warp_m * 64 + mi * 16;
                af[mi][0] = As[m0 + qrow    ][kb + qcol    ];
                af[mi][1] = As[m0 + qrow + 8][kb + qcol    ];
                af[mi][2] = As[m0 + qrow    ][kb + qcol + 4];
                af[mi][3] = As[m0 + qrow + 8][kb + qcol + 4];
            }
            uint32_t bf[4][2];
            #pragma unroll
            for (int ni = 0; ni < 4; ni++) {
                int n0 = warp_n * 32 + ni * 8;
                bf[ni][0] = Bs[kb + qcol    ][n0 + qrow];
                bf[ni][1] = Bs[kb + qcol + 4][n0 + qrow];
            }
            #pragma unroll
            for (int mi = 0; mi < 4; mi++)
                #pragma unroll
                for (int ni = 0; ni < 4; ni++)
                    mma_tf32(acc[mi * 4 + ni], af[mi], bf[ni]);
        }
        __syncthreads();
    }

    // epilogue: c0 (r,c) c1 (r,c+1) c2 (r+8,c) c3 (r+8,c+1)
    #pragma unroll
    for (int mi = 0; mi < 4; mi++) {
        int rbase = bm0 + warp_m * 64 + mi * 16 + qrow;
        #pragma unroll
        for (int ni = 0; ni < 4; ni++) {
            int cbase = bn0 + warp_n * 32 + ni * 8 + qcol * 2;
            float* a4 = acc[mi * 4 + ni];
            #pragma unroll
            for (int e = 0; e < 4; e++) {
                int row = rbase + (e >> 1) * 8;
                int col = cbase + (e & 1);
                if (col < Nn) {
                    float v = a4[e];
                    if (EPI == 1)      v = softplusf(v + bias[col]);
                    else if (EPI == 2) v = v + res[(size_t)row * Nn + col];
                    C[(size_t)row * ldc + col] = v;
                }
            }
        }
    }
}

// ---------------- causal depthwise conv (k=4) + SiLU ----------------
__global__ void conv_silu_kernel(const float* __restrict__ cw,
                                 const float* __restrict__ cb)
{
    int idx = blockIdx.x * 256 + threadIdx.x;
    if (idx >= MROWS * DIN) return;
    int d = idx % DIN;
    int m = idx / DIN;
    int t = m % LSEQ;
    int base = m - t;   // b*L
    float acc = cb[d];
    #pragma unroll
    for (int j = 0; j < KCONV; j++) {
        int tt = t - (KCONV - 1) + j;
        if (tt >= 0)
            acc = fmaf(cw[d * KCONV + j], g_xz[(size_t)(base + tt) * XZC + d], acc);
    }
    float s = acc / (1.f + __expf(-acc));   // silu
    g_uc[idx] = s;
}

// ---------------- selective scan (+ u*D, + z gating) ----------------
__global__ void scan_kernel(const float* __restrict__ A_log,
                            const float* __restrict__ Dp)
{
    int tid = blockIdx.x * blockDim.x + threadIdx.x;
    int grp = tid >> 4;          // channel index 0..B*DIN-1
    int n   = tid & 15;
    if (grp >= BSZ * DIN) return;
    int b = grp / DIN;
    int d = grp % DIN;

    float An = -expf(A_log[d * NST + n]);
    float Dd = Dp[d];

    const float* dbc_b = g_dbc   + (size_t)b * LSEQ * DBCC;
    const float* del_b = g_delta + (size_t)b * LSEQ * DIN + d;
    const float* u_b   = g_uc    + (size_t)b * LSEQ * DIN + d;
    const float* z_b   = g_xz    + (size_t)b * LSEQ * XZC + DIN + d;
    float*       o_b   = g_gt    + (size_t)b * LSEQ * DIN + d;

    float h = 0.f;
    for (int t = 0; t < LSEQ; t++) {
        float delta = del_b[(size_t)t * DIN];
        float u     = u_b[(size_t)t * DIN];
        float Bv    = dbc_b[(size_t)t * DBCC + DTR + n];
        float Cv    = dbc_b[(size_t)t * DBCC + DTR + NST + n];
        float da = __expf(delta * An);
        h = fmaf(da, h, delta * Bv * u);
        float p = h * Cv;
        p += __shfl_xor_sync(0xffffffffu, p, 8, 16);
        p += __shfl_xor_sync(0xffffffffu, p, 4, 16);
        p += __shfl_xor_sync(0xffffffffu, p, 2, 16);
        p += __shfl_xor_sync(0xffffffffu, p, 1, 16);
        if (n == 0) {
            float y = p + u * Dd;
            float z = z_b[(size_t)t * XZC];
            float g = y * (z / (1.f + __expf(-z)));
            o_b[(size_t)t * DIN] = g;
        }
    }
}

// ---------------- launcher ----------------
extern "C" void kernel_launch(void* const* d_in, const int* in_sizes, int n_in,
                              void* d_out, int out_size)
{
    const float* x         = (const float*)d_in[0];
    const float* in_proj_w = (const float*)d_in[1];
    const float* conv_w    = (const float*)d_in[2];
    const float* conv_b    = (const float*)d_in[3];
    const float* x_proj_w  = (const float*)d_in[4];
    const float* dt_proj_w = (const float*)d_in[5];
    const float* dt_proj_b = (const float*)d_in[6];
    const float* A_log     = (const float*)d_in[7];
    const float* Dp        = (const float*)d_in[8];
    const float* out_proj_w= (const float*)d_in[9];
    const float* ln_g      = (const float*)d_in[10];
    const float* ln_b      = (const float*)d_in[11];
    float* out = (float*)d_out;

    float* xn    = nullptr; cudaGetSymbolAddress((void**)&xn,    g_xn);
    float* xz    = nullptr; cudaGetSymbolAddress((void**)&xz,    g_xz);
    float* uc    = nullptr; cudaGetSymbolAddress((void**)&uc,    g_uc);
    float* dbc   = nullptr; cudaGetSymbolAddress((void**)&dbc,   g_dbc);
    float* delta = nullptr; cudaGetSymbolAddress((void**)&delta, g_delta);
    float* gt    = nullptr; cudaGetSymbolAddress((void**)&gt,    g_gt);

    // 1) layernorm
    ln_kernel<<<MROWS, 256>>>(x, ln_g, ln_b);

    // 2) xz = xn @ in_proj_w   (4096 x 4096, K=1024)
    {
        dim3 grid(XZC / 128, MROWS / 128);
        mma_gemm<0><<<grid, 256>>>(xn, DM, in_proj_w, XZC, xz, XZC,
                                   MROWS, XZC, DM, nullptr, nullptr);
    }

    // 3) u = silu(causal_conv(xz[:, :Din]))
    conv_silu_kernel<<<(MROWS * DIN + 255) / 256, 256>>>(conv_w, conv_b);

    // 4) dbc = u @ x_proj_w    (4096 x 96, K=2048)
    {
        dim3 grid(1, MROWS / 128);
        mma_gemm<0><<<grid, 256>>>(uc, DIN, x_proj_w, DBCC, dbc, DBCC,
                                   MROWS, DBCC, DIN, nullptr, nullptr);
    }

    // 5) delta = softplus(dbc[:, :64] @ dt_proj_w + dt_proj_b)  (4096 x 2048, K=64)
    {
        dim3 grid(DIN / 128, MROWS / 128);
        mma_gemm<1><<<grid, 256>>>(dbc, DBCC, dt_proj_w, DIN, delta, DIN,
                                   MROWS, DIN, DTR, dt_proj_b, nullptr);
    }

    // 6) selective scan + D skip + z gating -> gt
    {
        int threads = BSZ * DIN * NST;
        scan_kernel<<<(threads + 255) / 256, 256>>>(A_log, Dp);
    }

    // 7) out = x + gt @ out_proj_w  (4096 x 1024, K=2048)
    {
        dim3 grid(DM / 128, MROWS / 128);
        mma_gemm<2><<<grid, 256>>>(gt, DIN, out_proj_w, DM, out, DM,
                                   MROWS, DM, DIN, nullptr, x);
    }
    (void)in_sizes; (void)n_in; (void)out_size;
}